// round 6
// baseline (speedup 1.0000x reference)
#include <cuda_runtime.h>
#include <stdint.h>

// Hash-grid trilinear interpolation — two-pass table slicing + warp-coop gathers.
//
// Pass P gathers only corners whose bucket falls in table slice P (top bit of
// vid). Each 64MB slice fits L2 (~126MB) with wide margin during its pass, so
// the ~3.8x average bucket reuse is captured by plain LRU: gather DRAM drops
// from ~550MB to ~140MB total. Pass 0 writes partial sums to out; pass 1 adds
// its contribution and writes the final value.
//
// Coop layout (keeps L1tex wavefronts low): P1=1 so corner pairs (2p,2p+1)
// are adjacent buckets = 64 contiguous bytes. 4 lanes per pair, 16 lanes per
// point, warp = 2 points per round, shfl.xor reduction.

#define BUCKETS_MASK ((1u << 22) - 1u)
#define SLICE_SHIFT 21            // slice = vid >> 21  (two 64MB slices)
#define P1 1u
#define P2 2654435761u
#define P3 805459861u

template <int U, int PASS>
__global__ void __launch_bounds__(256) hashgrid_slice_kernel(
    const float* __restrict__ pts,   // (N,3)
    const char*  __restrict__ vf,    // (BUCKETS, 8 fp32) = 32 B per bucket
    float4*      __restrict__ out,   // (N, 8 fp32) = 2 float4 per point
    int n)
{
    int warp_g = (blockIdx.x * blockDim.x + threadIdx.x) >> 5;
    int lane   = threadIdx.x & 31;
    int l      = lane & 15;          // lane within 16-lane point-group
    int group  = lane >> 4;          // which of the warp's 2 points this round

    int pair = l >> 2;               // corner pair 0..3
    int j    = l & 3;                // float4 slot within the 64B pair block
    int c    = 2 * pair + (j >> 1);  // corner index 0..7
    uint32_t cx = (uint32_t)(c & 1);
    uint32_t cy = (uint32_t)((c >> 1) & 1);
    uint32_t cz = (uint32_t)((c >> 2) & 1);
    uint32_t hoff = cx * P1 + cy * P2 + cz * P3;

    int base = warp_g * (2 * U);

    float4 f[U];
    float  wgt[U];
    int    idx[U];
    bool   valid[U];

#pragma unroll
    for (int r = 0; r < U; r++) {
        int i = base + 2 * r + group;
        idx[r]   = i;
        valid[r] = (i < n);
        int ii = valid[r] ? i : 0;

        // broadcast load of the point (16 lanes same addr -> merged wavefront)
        float x = __ldcs(pts + 3 * ii + 0);
        float y = __ldcs(pts + 3 * ii + 1);
        float z = __ldcs(pts + 3 * ii + 2);

        float qx = x * 1024.0f, qy = y * 1024.0f, qz = z * 1024.0f;
        float bxf = floorf(qx), byf = floorf(qy), bzf = floorf(qz);
        float fx = qx - bxf, fy = qy - byf, fz = qz - bzf;

        uint32_t bx = (uint32_t)(int)bxf;
        uint32_t by = (uint32_t)(int)byf;
        uint32_t bz = (uint32_t)(int)bzf;
        uint32_t h  = bx * P1 + by * P2 + bz * P3;

        uint32_t vid = (h + hoff) & BUCKETS_MASK;
        bool active = ((vid >> SLICE_SHIFT) == (uint32_t)PASS) && valid[r];

        f[r] = make_float4(0.f, 0.f, 0.f, 0.f);
        if (active) {
            const char* ptr = vf + ((size_t)vid << 5) + ((uint32_t)(j & 1) << 4);
            f[r] = __ldg((const float4*)ptr);   // U independent gathers in flight
        }

        float wx = cx ? fx : 1.0f - fx;
        float wy = cy ? fy : 1.0f - fy;
        float wz = cz ? fz : 1.0f - fz;
        wgt[r] = wx * wy * wz;
    }

#pragma unroll
    for (int r = 0; r < U; r++) {
        float4 v;
        v.x = wgt[r] * f[r].x;
        v.y = wgt[r] * f[r].y;
        v.z = wgt[r] * f[r].z;
        v.w = wgt[r] * f[r].w;

        // butterfly sum over the 8 lanes holding the same half (j parity)
#pragma unroll
        for (int m = 2; m <= 8; m <<= 1) {
            v.x += __shfl_xor_sync(0xFFFFFFFFu, v.x, m);
            v.y += __shfl_xor_sync(0xFFFFFFFFu, v.y, m);
            v.z += __shfl_xor_sync(0xFFFFFFFFu, v.z, m);
            v.w += __shfl_xor_sync(0xFFFFFFFFu, v.w, m);
        }

        // lane 0 = out_lo, lane 1 = out_hi (per group)
        if (l < 2 && valid[r]) {
            float4* op = out + 2 * (size_t)idx[r] + l;
            if (PASS == 0) {
                // partial sum; default policy so pass 1 may still find it in L2
                *op = v;
            } else {
                float4 p = *op;
                v.x += p.x; v.y += p.y; v.z += p.z; v.w += p.w;
                __stcs(op, v);
            }
        }
    }
}

extern "C" void kernel_launch(void* const* d_in, const int* in_sizes, int n_in,
                              void* d_out, int out_size)
{
    const float* pts = (const float*)d_in[0];
    const char*  vf  = (const char*)d_in[1];
    float4*      out = (float4*)d_out;

    int n = in_sizes[0] / 3;

    constexpr int U = 4;                 // points-per-warp = 2*U = 8
    long long warps   = ((long long)n + (2 * U) - 1) / (2 * U);
    long long threads = warps * 32;
    int block = 256;
    long long grid = (threads + block - 1) / block;

    hashgrid_slice_kernel<U, 0><<<(int)grid, block>>>(pts, vf, out, n);
    hashgrid_slice_kernel<U, 1><<<(int)grid, block>>>(pts, vf, out, n);
}

// round 7
// speedup vs baseline: 1.8789x; 1.8789x over previous
#include <cuda_runtime.h>
#include <stdint.h>

// Hash-grid trilinear interpolation — two-pass table slicing, (point,half) threads.
//
// DRAM: pass P gathers only corners whose bucket is in table slice P (top bit
// of vid, 64MB per slice). Each slice fits L2 during its pass, so the ~3.8x
// average bucket reuse is captured by LRU (confirmed round 6: 248MB/pass vs
// 628MB unsliced). Pass 0 writes partial sums; pass 1 adds and finalizes.
//
// L1/MIO: thread = (point, 16B feature half). 8 predicated LDG.128 per thread,
// private accumulation, NO shuffles (round 6 showed shfl MIO cost == the
// gather wavefronts it saved). Lane pairs share gather lines; out stores are
// perfectly coalesced.

#define BUCKETS_MASK ((1u << 22) - 1u)
#define SLICE_SHIFT 21
#define P1 1u
#define P2 2654435761u
#define P3 805459861u

__constant__ uint32_t HOFF[8] = {
    0u, P1, P2, P1 + P2, P3, P1 + P3, P2 + P3, P1 + P2 + P3
};

template <int PASS>
__global__ void __launch_bounds__(256) hashgrid_half_kernel(
    const float* __restrict__ pts,   // (N,3)
    const char*  __restrict__ vf,    // (BUCKETS, 8 fp32) = 32 B per bucket
    float4*      __restrict__ out,   // (N, 8 fp32) = 2 float4 per point
    int n)
{
    int t = blockIdx.x * blockDim.x + threadIdx.x;
    int pt   = t >> 1;
    int half = t & 1;
    if (pt >= n) return;

    float x = pts[3 * pt + 0];
    float y = pts[3 * pt + 1];
    float z = pts[3 * pt + 2];

    float qx = x * 1024.0f, qy = y * 1024.0f, qz = z * 1024.0f;
    float bxf = floorf(qx), byf = floorf(qy), bzf = floorf(qz);
    float fx = qx - bxf, fy = qy - byf, fz = qz - bzf;

    uint32_t bx = (uint32_t)(int)bxf;
    uint32_t by = (uint32_t)(int)byf;
    uint32_t bz = (uint32_t)(int)bzf;
    uint32_t h  = bx * P1 + by * P2 + bz * P3;

    float gx = 1.0f - fx, gy = 1.0f - fy, gz = 1.0f - fz;
    float w[8];
    w[0] = gx * gy * gz;  w[1] = fx * gy * gz;
    w[2] = gx * fy * gz;  w[3] = fx * fy * gz;
    w[4] = gx * gy * fz;  w[5] = fx * gy * fz;
    w[6] = gx * fy * fz;  w[7] = fx * fy * fz;

    const char* base = vf + ((uint32_t)half << 4);

    // Issue all (predicated) gathers first: up to 8 LDG.128 in flight.
    float4 f[8];
#pragma unroll
    for (int c = 0; c < 8; c++) {
        uint32_t vid = (h + HOFF[c]) & BUCKETS_MASK;
        bool active = ((vid >> SLICE_SHIFT) == (uint32_t)PASS);
        f[c] = make_float4(0.f, 0.f, 0.f, 0.f);
        if (active) {
            f[c] = __ldg((const float4*)(base + ((size_t)vid << 5)));
        }
    }

    float4 acc = make_float4(0.f, 0.f, 0.f, 0.f);
#pragma unroll
    for (int c = 0; c < 8; c++) {
        float wc = w[c];
        acc.x = fmaf(wc, f[c].x, acc.x);
        acc.y = fmaf(wc, f[c].y, acc.y);
        acc.z = fmaf(wc, f[c].z, acc.z);
        acc.w = fmaf(wc, f[c].w, acc.w);
    }

    float4* op = out + 2 * (size_t)pt + half;   // coalesced across the warp
    if (PASS == 0) {
        *op = acc;
    } else {
        float4 p = *op;
        acc.x += p.x; acc.y += p.y; acc.z += p.z; acc.w += p.w;
        __stcs(op, acc);
    }
}

extern "C" void kernel_launch(void* const* d_in, const int* in_sizes, int n_in,
                              void* d_out, int out_size)
{
    const float* pts = (const float*)d_in[0];
    const char*  vf  = (const char*)d_in[1];
    float4*      out = (float4*)d_out;

    int n = in_sizes[0] / 3;

    long long threads = 2LL * n;
    int block = 256;
    long long grid = (threads + block - 1) / block;

    hashgrid_half_kernel<0><<<(int)grid, block>>>(pts, vf, out, n);
    hashgrid_half_kernel<1><<<(int)grid, block>>>(pts, vf, out, n);
}